// round 1
// baseline (speedup 1.0000x reference)
#include <cuda_runtime.h>

#define NROWS 8192
#define DIM   128
#define TILE  128
#define NTILES (NROWS / TILE)   // 64 row-tiles per matrix

// Accumulators (scratch via __device__ globals — no allocations allowed).
__device__ float g_G[2][DIM * DIM];   // g_G[0] = X^T X, g_G[1] = Y^T Y
__device__ float g_S2;                // sum_i <x_i,y_i>^2
__device__ float g_S3;                // sum_i <x_i,y_i>

// ---------------------------------------------------------------------------
// Zero the accumulators (graph replays reuse them; must reset every launch).
// ---------------------------------------------------------------------------
__global__ void zero_kernel() {
    int i = blockIdx.x * blockDim.x + threadIdx.x;
    if (i < 2 * DIM * DIM) ((float*)g_G)[i] = 0.0f;
    if (i == 0) { g_S2 = 0.0f; g_S3 = 0.0f; }
}

// ---------------------------------------------------------------------------
// Gram kernel: block b < 64 handles X rows [128b, 128b+128), b >= 64 handles Y.
// Loads a 128x128 fp32 tile into smem (64 KB dynamic), computes A^T A with
// 8x8 register tiling per thread (256 threads = 16x16 thread grid), then
// merges into the global Gram matrix with atomicAdd.
// ---------------------------------------------------------------------------
extern __shared__ float sA[];   // TILE * DIM floats = 64 KB

__global__ __launch_bounds__(256, 1)
void gram_kernel(const float* __restrict__ X, const float* __restrict__ Y) {
    const int which = (blockIdx.x >= NTILES) ? 1 : 0;
    const float* src = which ? Y : X;
    float* G = g_G[which];
    const int row0 = (blockIdx.x & (NTILES - 1)) * TILE;

    // Cooperative tile load: 16384 floats as float4 (128B coalesced lines).
    const float4* s4 = (const float4*)(src + (size_t)row0 * DIM);
    float4* a4 = (float4*)sA;
    #pragma unroll 4
    for (int i = threadIdx.x; i < TILE * DIM / 4; i += 256) a4[i] = s4[i];
    __syncthreads();

    const int tx = threadIdx.x & 15;   // output column tile
    const int ty = threadIdx.x >> 4;   // output row tile

    float acc[8][8];
    #pragma unroll
    for (int i = 0; i < 8; i++)
        #pragma unroll
        for (int j = 0; j < 8; j++) acc[i][j] = 0.0f;

    // Rank-128 update: C[d][e] += sum_r A[r][d] * A[r][e]
    for (int r = 0; r < TILE; ++r) {
        const float* row = sA + r * DIM;
        float a[8], b[8];
        #pragma unroll
        for (int i = 0; i < 8; i++) a[i] = row[ty * 8 + i];
        #pragma unroll
        for (int j = 0; j < 8; j++) b[j] = row[tx * 8 + j];
        #pragma unroll
        for (int i = 0; i < 8; i++)
            #pragma unroll
            for (int j = 0; j < 8; j++)
                acc[i][j] = fmaf(a[i], b[j], acc[i][j]);
    }

    // Merge partial Gram into global (64 contenders per address).
    #pragma unroll
    for (int i = 0; i < 8; i++)
        #pragma unroll
        for (int j = 0; j < 8; j++)
            atomicAdd(&G[(ty * 8 + i) * DIM + (tx * 8 + j)], acc[i][j]);
}

// ---------------------------------------------------------------------------
// Diagonal kernel: one warp per row (strided), d_i = <x_i, y_i> via float4
// loads + butterfly reduce; per-warp partials of S2/S3 merged with atomics.
// ---------------------------------------------------------------------------
__global__ void diag_kernel(const float* __restrict__ X, const float* __restrict__ Y) {
    const int lane   = threadIdx.x & 31;
    const int warp   = (blockIdx.x * blockDim.x + threadIdx.x) >> 5;
    const int nwarps = (gridDim.x * blockDim.x) >> 5;

    float s2 = 0.0f, s3 = 0.0f;
    for (int row = warp; row < NROWS; row += nwarps) {
        const float4 xv = ((const float4*)(X + (size_t)row * DIM))[lane];
        const float4 yv = ((const float4*)(Y + (size_t)row * DIM))[lane];
        float d = xv.x * yv.x + xv.y * yv.y + xv.z * yv.z + xv.w * yv.w;
        #pragma unroll
        for (int o = 16; o; o >>= 1) d += __shfl_xor_sync(0xffffffffu, d, o);
        if (lane == 0) { s3 += d; s2 += d * d; }
    }
    if (lane == 0) {
        atomicAdd(&g_S3, s3);
        atomicAdd(&g_S2, s2);
    }
}

// ---------------------------------------------------------------------------
// Final reduce: S1 = <Gx, Gy>_F (double accumulation; only 16K terms),
// then combine into the scalar loss.
// ---------------------------------------------------------------------------
__global__ void reduce_kernel(float* __restrict__ out) {
    __shared__ double sred[256];
    double s1 = 0.0;
    for (int i = threadIdx.x; i < DIM * DIM; i += 256)
        s1 += (double)g_G[0][i] * (double)g_G[1][i];
    sred[threadIdx.x] = s1;
    __syncthreads();
    for (int s = 128; s; s >>= 1) {
        if (threadIdx.x < s) sred[threadIdx.x] += sred[threadIdx.x + s];
        __syncthreads();
    }
    if (threadIdx.x == 0) {
        const double S1 = sred[0];
        const double loss =
            (S1 - (double)g_S2) / ((double)NROWS * (double)(NROWS - 1))
            - 2.0 * (double)g_S3 / (double)NROWS;
        out[0] = (float)loss;
    }
}

// ---------------------------------------------------------------------------
extern "C" void kernel_launch(void* const* d_in, const int* in_sizes, int n_in,
                              void* d_out, int out_size) {
    const float* X = (const float*)d_in[0];
    const float* Y = (const float*)d_in[1];
    float* out = (float*)d_out;

    static bool attr_set = false;   // idempotent host-side attribute (not a work guard)
    if (!attr_set) {
        cudaFuncSetAttribute(gram_kernel,
                             cudaFuncAttributeMaxDynamicSharedMemorySize,
                             TILE * DIM * (int)sizeof(float));
        attr_set = true;
    }

    zero_kernel<<<(2 * DIM * DIM + 255) / 256, 256>>>();
    gram_kernel<<<2 * NTILES, 256, TILE * DIM * (int)sizeof(float)>>>(X, Y);
    diag_kernel<<<128, 256>>>(X, Y);
    reduce_kernel<<<1, 256>>>(out);
}

// round 4
// speedup vs baseline: 2.2708x; 2.2708x over previous
#include <cuda_runtime.h>
#include <cuda_bf16.h>
#include <cstdint>

#define NROWS 8192
#define DIM   128
#define CHUNK 128                 // samples per tile
#define GRAM_BLOCKS 64            // block b: X chunk b and Y chunk b

// ---------------- device-global scratch (no allocations allowed) -----------
__device__ float   g_G[2][DIM * DIM];  // [0]=X^T X, [1]=Y^T Y
__device__ double  g_S1;               // <Gx,Gy>_F
__device__ float   g_S2;               // sum d_i^2
__device__ float   g_S3;               // sum d_i
__device__ unsigned g_ticket;

// ---------------- helpers ---------------------------------------------------
__device__ __forceinline__ uint32_t smem_u32(const void* p) {
    uint32_t a;
    asm("{ .reg .u64 t; cvta.to.shared.u64 t, %1; cvt.u32.u64 %0, t; }" : "=r"(a) : "l"(p));
    return a;
}

// Tile stored SAMPLE-major: S[k][d], k=0..127 samples (rows), d=0..127 features.
// 256B logical rows split into two 16KB subtiles by d>>6; 128B rows, SW128 swizzle.
__device__ __forceinline__ uint32_t toff(int k, int d) {
    uint32_t o = (uint32_t)(k * 128 + (d & 63) * 2);
    o ^= (o >> 3) & 0x70;
    return (uint32_t)((d >> 6) * 16384) + o;
}

#define LO_OFF     32768          // lo tile after hi tile (each 32KB)
#define SMEM_TOTAL 65536

__device__ __forceinline__ void ldsm4t(uint32_t* r, uint32_t addr) {
    asm volatile("ldmatrix.sync.aligned.m8n8.x4.trans.shared.b16 {%0,%1,%2,%3}, [%4];"
                 : "=r"(r[0]), "=r"(r[1]), "=r"(r[2]), "=r"(r[3]) : "r"(addr));
}

__device__ __forceinline__ void mma_bf16(float* d, const uint32_t* a,
                                         uint32_t b0, uint32_t b1) {
    asm volatile(
        "mma.sync.aligned.m16n8k16.row.col.f32.bf16.bf16.f32 "
        "{%0,%1,%2,%3}, {%4,%5,%6,%7}, {%8,%9}, {%0,%1,%2,%3};"
        : "+f"(d[0]), "+f"(d[1]), "+f"(d[2]), "+f"(d[3])
        : "r"(a[0]), "r"(a[1]), "r"(a[2]), "r"(a[3]), "r"(b0), "r"(b1));
}

// ---------------------------------------------------------------------------
__global__ void zero_kernel() {
    int i = blockIdx.x * blockDim.x + threadIdx.x;
    if (i < 2 * DIM * DIM) ((float*)g_G)[i] = 0.0f;
    if (i == 0) { g_S1 = 0.0; g_S2 = 0.0f; g_S3 = 0.0f; g_ticket = 0u; }
}

// ---------------------------------------------------------------------------
// Tensor-core Gram via mma.sync bf16 hi/lo split.
// Block b processes X rows [128b,128b+128) then Y rows, accumulating partial
// Grams in registers and merging with atomicAdd.
// ---------------------------------------------------------------------------
__global__ __launch_bounds__(256, 1)
void gram_kernel(const float* __restrict__ X, const float* __restrict__ Y) {
    extern __shared__ char smem[];
    const uint32_t sb = smem_u32(smem);
    const int tid  = threadIdx.x;
    const int w    = tid >> 5;
    const int lane = tid & 31;

    // ldmatrix per-lane tile-row selectors
    const int lr    = lane & 7;
    const int a_kad = (lane & 16) ? 8 : 0;  // A: groups 2,3 take k+8
    const int a_mad = (lane & 8)  ? 8 : 0;  // A: groups 1,3 take m+8
    const int b_kad = (lane & 8)  ? 8 : 0;  // B: groups 1,3 take k+8
    const int b_nad = (lane & 16) ? 8 : 0;  // B: groups 2,3 take n+8
    const int m0    = w * 16;               // warp's output row slab

    for (int which = 0; which < 2; ++which) {
        const float* base = (which ? Y : X) + (size_t)blockIdx.x * CHUNK * DIM;

        // ---- convert: fp32 -> bf16 hi/lo, sample-major swizzled tiles ----
        #pragma unroll 4
        for (int it = 0; it < 16; ++it) {
            const int r = w + 8 * it;                       // sample row
            const float4 v = *reinterpret_cast<const float4*>(base + r * DIM + lane * 4);
            __nv_bfloat162 h01 = __floats2bfloat162_rn(v.x, v.y);
            __nv_bfloat162 h23 = __floats2bfloat162_rn(v.z, v.w);
            __nv_bfloat162 l01 = __floats2bfloat162_rn(v.x - __bfloat162float(h01.x),
                                                       v.y - __bfloat162float(h01.y));
            __nv_bfloat162 l23 = __floats2bfloat162_rn(v.z - __bfloat162float(h23.x),
                                                       v.w - __bfloat162float(h23.y));
            const uint32_t o = toff(r, lane * 4);
            uint2 hv, lv;
            hv.x = *reinterpret_cast<uint32_t*>(&h01);
            hv.y = *reinterpret_cast<uint32_t*>(&h23);
            lv.x = *reinterpret_cast<uint32_t*>(&l01);
            lv.y = *reinterpret_cast<uint32_t*>(&l23);
            *reinterpret_cast<uint2*>(smem + o)          = hv;
            *reinterpret_cast<uint2*>(smem + LO_OFF + o) = lv;
        }
        __syncthreads();

        // ---- MMA mainloop: acc[nt][i], nt = 0..15 (8-col tiles) ----
        float acc[16][4];
        #pragma unroll
        for (int nt = 0; nt < 16; ++nt)
            #pragma unroll
            for (int i = 0; i < 4; ++i) acc[nt][i] = 0.0f;

        for (int ks = 0; ks < 8; ++ks) {
            const int k0 = ks * 16;
            uint32_t ahi[4], alo[4];
            const uint32_t aoff = toff(k0 + lr + a_kad, m0 + a_mad);
            ldsm4t(ahi, sb + aoff);
            ldsm4t(alo, sb + LO_OFF + aoff);

            #pragma unroll
            for (int ntp = 0; ntp < 8; ++ntp) {
                const int n0 = ntp * 16;
                uint32_t bhi[4], blo[4];
                const uint32_t boff = toff(k0 + lr + b_kad, n0 + b_nad);
                ldsm4t(bhi, sb + boff);
                ldsm4t(blo, sb + LO_OFF + boff);
                // n-tile 2*ntp: HH + HL + LH
                mma_bf16(acc[2 * ntp], ahi, bhi[0], bhi[1]);
                mma_bf16(acc[2 * ntp], ahi, blo[0], blo[1]);
                mma_bf16(acc[2 * ntp], alo, bhi[0], bhi[1]);
                // n-tile 2*ntp+1
                mma_bf16(acc[2 * ntp + 1], ahi, bhi[2], bhi[3]);
                mma_bf16(acc[2 * ntp + 1], ahi, blo[2], blo[3]);
                mma_bf16(acc[2 * ntp + 1], alo, bhi[2], bhi[3]);
            }
        }

        // ---- merge partial Gram (distinct rows per warp within block) ----
        float* G = g_G[which];
        const int row0 = m0 + (lane >> 2);
        const int col0 = (lane & 3) * 2;
        #pragma unroll
        for (int nt = 0; nt < 16; ++nt)
            #pragma unroll
            for (int i = 0; i < 4; ++i) {
                const int rr = row0 + (i >> 1) * 8;
                const int cc = nt * 8 + col0 + (i & 1);
                atomicAdd(&G[rr * DIM + cc], acc[nt][i]);
            }
        __syncthreads();   // protect smem before next matrix's convert
    }
}

// ---------------------------------------------------------------------------
__global__ void diag_kernel(const float* __restrict__ X, const float* __restrict__ Y) {
    const int lane   = threadIdx.x & 31;
    const int warp   = (blockIdx.x * blockDim.x + threadIdx.x) >> 5;
    const int nwarps = (gridDim.x * blockDim.x) >> 5;

    float s2 = 0.0f, s3 = 0.0f;
    for (int row = warp; row < NROWS; row += nwarps) {
        const float4 xv = ((const float4*)(X + (size_t)row * DIM))[lane];
        const float4 yv = ((const float4*)(Y + (size_t)row * DIM))[lane];
        float d = xv.x * yv.x + xv.y * yv.y + xv.z * yv.z + xv.w * yv.w;
        #pragma unroll
        for (int o = 16; o; o >>= 1) d += __shfl_xor_sync(0xffffffffu, d, o);
        if (lane == 0) { s3 += d; s2 += d * d; }
    }
    if (lane == 0) { atomicAdd(&g_S3, s3); atomicAdd(&g_S2, s2); }
}

// ---------------------------------------------------------------------------
// Frobenius product + final combine (last-block ticket). 64 blocks x 256.
// ---------------------------------------------------------------------------
__global__ void reduce_kernel(float* __restrict__ out) {
    __shared__ double sred[256];
    __shared__ unsigned last;
    const int tid = threadIdx.x;
    const int i   = blockIdx.x * 256 + tid;

    sred[tid] = (double)g_G[0][i] * (double)g_G[1][i];
    __syncthreads();
    for (int s = 128; s; s >>= 1) {
        if (tid < s) sred[tid] += sred[tid + s];
        __syncthreads();
    }
    if (tid == 0) {
        atomicAdd(&g_S1, sred[0]);
        __threadfence();
        last = atomicAdd(&g_ticket, 1u);
    }
    __syncthreads();
    if (tid == 0 && last == gridDim.x - 1) {
        const double S1 = atomicAdd(&g_S1, 0.0);   // coherent read at L2
        const double loss =
            (S1 - (double)g_S2) / ((double)NROWS * (double)(NROWS - 1))
            - 2.0 * (double)g_S3 / (double)NROWS;
        out[0] = (float)loss;
    }
}

// ---------------------------------------------------------------------------
extern "C" void kernel_launch(void* const* d_in, const int* in_sizes, int n_in,
                              void* d_out, int out_size) {
    const float* X = (const float*)d_in[0];
    const float* Y = (const float*)d_in[1];
    float* out = (float*)d_out;

    static bool attr_set = false;   // idempotent host-side attribute
    if (!attr_set) {
        cudaFuncSetAttribute(gram_kernel,
                             cudaFuncAttributeMaxDynamicSharedMemorySize, SMEM_TOTAL);
        attr_set = true;
    }

    zero_kernel<<<128, 256>>>();
    gram_kernel<<<GRAM_BLOCKS, 256, SMEM_TOTAL>>>(X, Y);
    diag_kernel<<<128, 256>>>(X, Y);
    reduce_kernel<<<DIM * DIM / 256, 256>>>(out);
}